// round 13
// baseline (speedup 1.0000x reference)
#include <cuda_runtime.h>
#include <cuda_fp16.h>
#include <cstdint>

typedef unsigned long long ull;

#define BMAX 32768

// ---------------- scratch (static device globals: no allocation) ----------------
__device__ __align__(16) float g_rot[18 * 8];
__device__ __align__(16) __half g_af[(size_t)BMAX * 128];  // A (activations) fp16
__device__ __align__(16) __half g_bh[1296 * 128];          // w2^T fp16 [N,K]
__device__ __align__(16) __half g_w1p[32 * 32 * 4 * 8];    // enc_w1 packed frags hi/lo

// ---------------- f32x2 packed helpers ----------------
__device__ __forceinline__ ull f2pack(float a, float b) {
    ull r;
    asm("mov.b64 %0, {%1, %2};" : "=l"(r) : "r"(__float_as_uint(a)), "r"(__float_as_uint(b)));
    return r;
}
__device__ __forceinline__ void f2unpack(ull v, float& a, float& b) {
    unsigned int lo, hi;
    asm("mov.b64 {%0, %1}, %2;" : "=r"(lo), "=r"(hi) : "l"(v));
    a = __uint_as_float(lo); b = __uint_as_float(hi);
}
__device__ __forceinline__ ull ffma2(ull a, ull b, ull c) {
    ull d;
    asm("fma.rn.f32x2 %0, %1, %2, %3;" : "=l"(d) : "l"(a), "l"(b), "l"(c));
    return d;
}
__device__ __forceinline__ ull fmul2(ull a, ull b) {
    ull d;
    asm("mul.rn.f32x2 %0, %1, %2;" : "=l"(d) : "l"(a), "l"(b));
    return d;
}

// ---------------- mma/ldmatrix helpers ----------------
__device__ __forceinline__ uint32_t smem_u32(const void* p) {
    uint32_t a;
    asm("{ .reg .u64 t; cvta.to.shared.u64 t, %1; cvt.u32.u64 %0, t; }" : "=r"(a) : "l"(p));
    return a;
}
__device__ __forceinline__ void ldsm4(uint32_t& r0, uint32_t& r1, uint32_t& r2, uint32_t& r3,
                                      uint32_t a) {
    asm volatile("ldmatrix.sync.aligned.m8n8.x4.shared.b16 {%0,%1,%2,%3}, [%4];"
                 : "=r"(r0), "=r"(r1), "=r"(r2), "=r"(r3) : "r"(a));
}
__device__ __forceinline__ void mma16816(float* d, uint32_t a0, uint32_t a1, uint32_t a2,
                                         uint32_t a3, uint32_t b0, uint32_t b1) {
    asm volatile(
        "mma.sync.aligned.m16n8k16.row.col.f32.f16.f16.f32 "
        "{%0,%1,%2,%3}, {%4,%5,%6,%7}, {%8,%9}, {%0,%1,%2,%3};"
        : "+f"(d[0]), "+f"(d[1]), "+f"(d[2]), "+f"(d[3])
        : "r"(a0), "r"(a1), "r"(a2), "r"(a3), "r"(b0), "r"(b1));
}
__device__ __forceinline__ uint32_t smaddr(uint32_t base, int row, int c) {
    return base + row * 256 + (((uint32_t)(c ^ (row & 7))) << 4);
}
__device__ __forceinline__ uint32_t h2pack(float a, float b) {
    __half2 h = __floats2half2_rn(a, b);
    return *(uint32_t*)&h;
}

// ---------------- K0: precompute Rot matrices ----------------
__global__ void k0_rot(const float* __restrict__ qw) {
    int t = threadIdx.x;
    if (t >= 18) return;
    float phi = qw[t * 3 + 0], th = qw[t * 3 + 1], om = qw[t * 3 + 2];
    float c = cosf(th * 0.5f), s = sinf(th * 0.5f);
    float ap = -(phi + om) * 0.5f, am = -(phi - om) * 0.5f;
    float sp, cp, sm, cm;
    sincosf(ap, &sp, &cp);
    sincosf(am, &sm, &cm);
    float* r = g_rot + t * 8;
    r[0] = cp * c;  r[1] = sp * c;
    r[2] = -cm * s; r[3] = sm * s;
    r[4] = cm * s;  r[5] = sm * s;
    r[6] = cp * c;  r[7] = -sp * c;
}

// ---------------- K0b: transpose head_w2 [128,1296] -> fp16 [1296,128] ----------------
__global__ void k_w2split(const float* __restrict__ w2) {
    int i = blockIdx.x * blockDim.x + threadIdx.x;
    if (i >= 1296 * 128) return;
    int n = i >> 7, k = i & 127;
    g_bh[i] = __float2half_rn(w2[k * 1296 + n]);
}

// ---------------- K0c: pack enc_w1 into mma-fragment order, fp16 hi/lo ----
__global__ void k_w1pack(const float* __restrict__ w1) {
    int i = blockIdx.x * blockDim.x + threadIdx.x;
    if (i >= 4096) return;
    int q = i & 3, ks = (i >> 2) & 31, n = i >> 7;
    int kc = ks * 16 + 4 * q;
    float v0 = w1[(kc + 0) * 32 + n];
    float v1 = w1[(kc + 1) * 32 + n];
    float v2 = w1[(kc + 2) * 32 + n];
    float v3 = w1[(kc + 3) * 32 + n];
    __half h[8];
    h[0] = __float2half_rn(v0); h[1] = __float2half_rn(v1);
    h[2] = __float2half_rn(v2); h[3] = __float2half_rn(v3);
    h[4] = __float2half_rn(v0 - __half2float(h[0]));
    h[5] = __float2half_rn(v1 - __half2float(h[1]));
    h[6] = __float2half_rn(v2 - __half2float(h[2]));
    h[7] = __float2half_rn(v3 - __half2float(h[3]));
    *(uint4*)(g_w1p + (size_t)i * 8) = *(uint4*)h;
}

// ---------------- circuit helpers ----------------
__device__ __forceinline__ float2 shflx(float2 v, int m) {
    float2 r;
    r.x = __shfl_xor_sync(0xffffffffu, v.x, m);
    r.y = __shfl_xor_sync(0xffffffffu, v.y, m);
    return r;
}
__device__ __forceinline__ float2 cmul(float2 a, float2 b) {
    return make_float2(a.x * b.x - a.y * b.y, a.x * b.y + a.y * b.x);
}
__device__ __forceinline__ float2 cmadd(float2 a, float2 b, float2 acc) {
    return make_float2(acc.x + a.x * b.x - a.y * b.y, acc.y + a.x * b.y + a.y * b.x);
}

// ---------------- K12: fused encoder (HMMA) + circuit, 32 samples/CTA ----------------
__global__ __launch_bounds__(256)
void k12_fused(const float* __restrict__ x,
               const float* __restrict__ b1,
               const float* __restrict__ w2,
               const float* __restrict__ b2,
               const float* __restrict__ hw1,
               const float* __restrict__ hb1, int base) {
    __shared__ float red[2][3][32][16];
    __shared__ float sang[32][6];

    int tid = threadIdx.x, lane = tid & 31, wid = tid >> 5;

    // ======== phase 1: encoder ========
    {
        int tile = wid >> 2, tw = wid & 3;
        int m0 = base + blockIdx.x * 32 + tile * 16;
        int g = lane >> 2, q = lane & 3;
        const float* xr0 = x + (size_t)(m0 + g) * 512;
        const float* xr1 = x + (size_t)(m0 + g + 8) * 512;

        float acc[4][4];
#pragma unroll
        for (int nf = 0; nf < 4; nf++)
#pragma unroll
            for (int v = 0; v < 4; v++) acc[nf][v] = 0.f;

#pragma unroll
        for (int kk = 0; kk < 8; kk++) {
            int ks = tw * 8 + kk;
            int kc = ks * 16 + 4 * q;
            float4 v0 = *(const float4*)(xr0 + kc);
            float4 v1 = *(const float4*)(xr1 + kc);

            uint32_t ah0 = h2pack(v0.x, v0.y), ah1 = h2pack(v1.x, v1.y);
            uint32_t ah2 = h2pack(v0.z, v0.w), ah3 = h2pack(v1.z, v1.w);
            __half2 t0 = *(__half2*)&ah0, t1 = *(__half2*)&ah1;
            __half2 t2 = *(__half2*)&ah2, t3 = *(__half2*)&ah3;
            uint32_t al0 = h2pack(v0.x - __low2float(t0), v0.y - __high2float(t0));
            uint32_t al1 = h2pack(v1.x - __low2float(t1), v1.y - __high2float(t1));
            uint32_t al2 = h2pack(v0.z - __low2float(t2), v0.w - __high2float(t2));
            uint32_t al3 = h2pack(v1.z - __low2float(t3), v1.w - __high2float(t3));

#pragma unroll
            for (int nf = 0; nf < 4; nf++) {
                int n = nf * 8 + g;
                uint4 bv = *(const uint4*)(g_w1p + (size_t)(((n * 32 + ks) * 4 + q)) * 8);
                mma16816(acc[nf], ah0, ah1, ah2, ah3, bv.x, bv.y);
                mma16816(acc[nf], ah0, ah1, ah2, ah3, bv.z, bv.w);
                mma16816(acc[nf], al0, al1, al2, al3, bv.x, bv.y);
            }
        }

        if (tw) {
            float4* dst = (float4*)red[tile][tw - 1][lane];
#pragma unroll
            for (int nf = 0; nf < 4; nf++) dst[nf] = *(float4*)acc[nf];
        }
        __syncthreads();

        if (tw == 0) {
#pragma unroll
            for (int w = 0; w < 3; w++) {
                const float* src = red[tile][w][lane];
#pragma unroll
                for (int nf = 0; nf < 4; nf++)
#pragma unroll
                    for (int v = 0; v < 4; v++) acc[nf][v] += src[nf * 4 + v];
            }

            float pr0[6], pr1[6];
#pragma unroll
            for (int i = 0; i < 6; i++) { pr0[i] = 0.f; pr1[i] = 0.f; }

#pragma unroll
            for (int nf = 0; nf < 4; nf++) {
                int c0 = nf * 8 + 2 * q;
                float bb0 = b1[c0], bb1 = b1[c0 + 1];
                float h00 = tanhf(acc[nf][0] + bb0);
                float h01 = tanhf(acc[nf][1] + bb1);
                float h10 = tanhf(acc[nf][2] + bb0);
                float h11 = tanhf(acc[nf][3] + bb1);
#pragma unroll
                for (int i = 0; i < 6; i++) {
                    float w0 = w2[c0 * 6 + i], w1v = w2[(c0 + 1) * 6 + i];
                    pr0[i] += h00 * w0 + h01 * w1v;
                    pr1[i] += h10 * w0 + h11 * w1v;
                }
            }
#pragma unroll
            for (int m = 1; m <= 2; m <<= 1) {
#pragma unroll
                for (int i = 0; i < 6; i++) {
                    pr0[i] += __shfl_xor_sync(0xffffffffu, pr0[i], m);
                    pr1[i] += __shfl_xor_sync(0xffffffffu, pr1[i], m);
                }
            }
            if (q == 0) {
#pragma unroll
                for (int i = 0; i < 6; i++) {
                    sang[tile * 16 + g][i] = pr0[i] + b2[i];
                    sang[tile * 16 + g + 8][i] = pr1[i] + b2[i];
                }
            }
        }
    }
    __syncthreads();

    // ======== phase 2: circuit (4 samples/warp, 8 lanes/sample) ========
    int l3 = lane & 7;
    int ls = wid * 4 + (lane >> 3);
    int s = base + blockIdx.x * 32 + ls;

    float cs[6], sn[6];
#pragma unroll
    for (int q = 0; q < 6; q++) {
        float a = sang[ls][q];
        __sincosf(0.5f * a, &sn[q], &cs[q]);
    }

    float2 A[8];
#pragma unroll
    for (int j = 0; j < 8; j++) A[j] = make_float2(0.f, 0.f);
    if (l3 == 0) A[0].x = 1.f;

#pragma unroll
    for (int L = 0; L < 3; L++) {
#pragma unroll
        for (int q = 0; q < 6; q++) {
            const ull* up = (const ull*)(g_rot + (L * 6 + q) * 8);
            ull u01 = up[0], u23 = up[1], u45 = up[2], u67 = up[3];
            float c = cs[q], s2 = sn[q];
            ull cp = f2pack(c, c), sp = f2pack(s2, s2), sn2 = f2pack(-s2, -s2);
            float2 f00, f01, f10, f11;
            f2unpack(ffma2(u23, sp, fmul2(u01, cp)), f00.x, f00.y);
            f2unpack(ffma2(u01, sn2, fmul2(u23, cp)), f01.x, f01.y);
            f2unpack(ffma2(u67, sp, fmul2(u45, cp)), f10.x, f10.y);
            f2unpack(ffma2(u45, sn2, fmul2(u67, cp)), f11.x, f11.y);

            if (q <= 2) {
                int m = 4 >> q;
                bool hi = (l3 & m) != 0;
                float2 ua = hi ? f11 : f00;
                float2 ub = hi ? f10 : f01;
#pragma unroll
                for (int j = 0; j < 8; j++) {
                    float2 P = shflx(A[j], m);
                    A[j] = cmadd(ub, P, cmul(ua, A[j]));
                }
            } else {
                int lb = 5 - q;
                int st = 1 << lb;
#pragma unroll
                for (int i0 = 0; i0 < 8; i0++) {
                    if (i0 & st) continue;
                    int i1 = i0 | st;
                    float2 n0 = cmadd(f01, A[i1], cmul(f00, A[i0]));
                    float2 n1 = cmadd(f11, A[i1], cmul(f10, A[i0]));
                    A[i0] = n0; A[i1] = n1;
                }
            }
        }
        // CNOT ladder
        {
#pragma unroll
            for (int j = 0; j < 8; j++) {
                float2 P = shflx(A[j], 2);
                if (l3 & 4) A[j] = P;
            }
        }
        if (l3 & 1) {
#pragma unroll
            for (int j = 0; j < 4; j++) { float2 t = A[j]; A[j] = A[j + 4]; A[j + 4] = t; }
        }
        { float2 t = A[2]; A[2] = A[3]; A[3] = t; }
        { float2 t = A[6]; A[6] = A[7]; A[7] = t; }
        {
#pragma unroll
            for (int j = 0; j < 8; j++) {
                float2 P = shflx(A[j], 1);
                if (l3 & 2) A[j] = P;
            }
        }
        { float2 t = A[4]; A[4] = A[6]; A[6] = t; }
        { float2 t = A[5]; A[5] = A[7]; A[7] = t; }
        {
            A[1] = shflx(A[1], 4);
            A[3] = shflx(A[3], 4);
            A[5] = shflx(A[5], 4);
            A[7] = shflx(A[7], 4);
        }
    }

    float p[8];
#pragma unroll
    for (int j = 0; j < 8; j++) p[j] = A[j].x * A[j].x + A[j].y * A[j].y;
    float sum = (p[0] + p[1]) + (p[2] + p[3]) + (p[4] + p[5]) + (p[6] + p[7]);
    float z[6];
    z[0] = (l3 & 4) ? -sum : sum;
    z[1] = (l3 & 2) ? -sum : sum;
    z[2] = (l3 & 1) ? -sum : sum;
    z[3] = sum - 2.f * ((p[4] + p[5]) + (p[6] + p[7]));
    z[4] = sum - 2.f * ((p[2] + p[3]) + (p[6] + p[7]));
    z[5] = sum - 2.f * ((p[1] + p[3]) + (p[5] + p[7]));
#pragma unroll
    for (int off = 4; off; off >>= 1) {
#pragma unroll
        for (int q = 0; q < 6; q++) z[q] += __shfl_xor_sync(0xffffffffu, z[q], off);
    }

    __half hv[16];
#pragma unroll
    for (int u = 0; u < 16; u++) {
        int j = l3 * 16 + u;
        float a = hb1[j];
#pragma unroll
        for (int i = 0; i < 6; i++) a += z[i] * hw1[i * 128 + j];
        hv[u] = __float2half_rn(fmaxf(a, 0.f));
    }
    uint4* dst = (uint4*)(g_af + (size_t)s * 128 + l3 * 16);
    dst[0] = *(uint4*)&hv[0];
    dst[1] = *(uint4*)&hv[8];
}

// ---------------- K3: HMMA fp16 GEMM  out = A[B,128] @ w2[128,1296] + b2 ----
#define K3_SMEM (32768 + 36864)

__global__ __launch_bounds__(256, 2)
void k3_mma(const float* __restrict__ b2, float* __restrict__ out, int base) {
    extern __shared__ char sm3[];
    __half* sA  = (__half*)sm3;            // 128 x 128
    __half* sBh = (__half*)(sm3 + 32768);  // 144 x 128

    int tid = threadIdx.x, lane = tid & 31, wid = tid >> 5;
    int n0 = blockIdx.x * 144;
    int m0 = base + blockIdx.y * 128;

    const uint4* gA = (const uint4*)g_af + (size_t)m0 * 16;
    uint4* dA = (uint4*)sA;
#pragma unroll
    for (int it = 0; it < 8; it++) {
        int i = it * 256 + tid;
        int r = i >> 4, c = i & 15;
        dA[r * 16 + (c ^ (r & 7))] = gA[i];
    }
    const uint4* gBh = (const uint4*)g_bh + (size_t)n0 * 16;
    uint4* dBh = (uint4*)sBh;
#pragma unroll
    for (int it = 0; it < 9; it++) {
        int i = it * 256 + tid;
        int r = i >> 4, c = i & 15;
        dBh[r * 16 + (c ^ (r & 7))] = gBh[i];
    }
    __syncthreads();

    uint32_t sAb = smem_u32(sA), sBhb = smem_u32(sBh);
    int la = lane & 7, hb = (lane >> 3) & 1, hc = lane >> 4;
    int arow = wid * 16 + la + (hb << 3);
    int brow = la + (hb << 3);

    float acc[18][4];
#pragma unroll
    for (int j = 0; j < 18; j++)
#pragma unroll
        for (int v = 0; v < 4; v++) acc[j][v] = 0.f;

#pragma unroll
    for (int ks = 0; ks < 8; ks++) {
        int ca = 2 * ks + hc;
        uint32_t a0, a1, a2, a3;
        ldsm4(a0, a1, a2, a3, smaddr(sAb, arow, ca));

#pragma unroll
        for (int p = 0; p < 9; p++) {
            uint32_t r0, r1, r2, r3;
            ldsm4(r0, r1, r2, r3, smaddr(sBhb, p * 16 + brow, ca));
            mma16816(acc[2 * p],     a0, a1, a2, a3, r0, r2);
            mma16816(acc[2 * p + 1], a0, a1, a2, a3, r1, r3);
        }
    }

    int orow0 = m0 + wid * 16 + (lane >> 2);
    float* op = out + (size_t)orow0 * 1296 + n0 + 2 * (lane & 3);
    const float* bp = b2 + n0 + 2 * (lane & 3);
#pragma unroll
    for (int j = 0; j < 18; j++) {
        float2 bias = *(const float2*)(bp + 8 * j);
        float2 v0 = make_float2(acc[j][0] + bias.x, acc[j][1] + bias.y);
        float2 v1 = make_float2(acc[j][2] + bias.x, acc[j][3] + bias.y);
        __stcs((float2*)(op + 8 * j), v0);
        __stcs((float2*)(op + 8 * j + 8 * 1296), v1);
    }
}

// ---------------- launch: asymmetric 4-chunk / 3-stream software pipeline ----------------
// sB: k12(c0), k12(c2) ; sC: k12(c1), k12(c3) ; sA: k3(c0..c3) gated per-chunk.
extern "C" void kernel_launch(void* const* d_in, const int* in_sizes, int n_in,
                              void* d_out, int out_size) {
    const float* x   = (const float*)d_in[0];
    const float* ew1 = (const float*)d_in[1];
    const float* eb1 = (const float*)d_in[2];
    const float* ew2 = (const float*)d_in[3];
    const float* eb2 = (const float*)d_in[4];
    const float* qw  = (const float*)d_in[5];
    const float* hw1 = (const float*)d_in[6];
    const float* hb1 = (const float*)d_in[7];
    const float* hw2 = (const float*)d_in[8];
    const float* hb2 = (const float*)d_in[9];
    float* out = (float*)d_out;

    int B = in_sizes[0] / 512;

    static bool inited = false;
    static cudaStream_t sA, sB, sC;
    static cudaEvent_t evFork, evW2, e[4], evJA, evJB, evJC;
    if (!inited) {
        cudaStreamCreateWithFlags(&sA, cudaStreamNonBlocking);
        cudaStreamCreateWithFlags(&sB, cudaStreamNonBlocking);
        cudaStreamCreateWithFlags(&sC, cudaStreamNonBlocking);
        cudaEventCreateWithFlags(&evFork, cudaEventDisableTiming);
        cudaEventCreateWithFlags(&evW2, cudaEventDisableTiming);
        for (int i = 0; i < 4; i++) cudaEventCreateWithFlags(&e[i], cudaEventDisableTiming);
        cudaEventCreateWithFlags(&evJA, cudaEventDisableTiming);
        cudaEventCreateWithFlags(&evJB, cudaEventDisableTiming);
        cudaEventCreateWithFlags(&evJC, cudaEventDisableTiming);
        cudaFuncSetAttribute(k3_mma, cudaFuncAttributeMaxDynamicSharedMemorySize, K3_SMEM);
        inited = true;
    }

    // chunk sizes: small first chunk to start the tensor pipe early
    int c0 = (B / 8) & ~127;              // 4096
    int rem = B - c0;
    int c1 = (rem / 3) & ~127;            // 9472
    int c2 = c1;
    int c3 = rem - c1 - c2;               // 9728
    int base0 = 0, base1 = c0, base2 = c0 + c1, base3 = c0 + c1 + c2;

    // prep needed by k12 (tiny) on the capture stream
    k0_rot<<<1, 32>>>(qw);
    k_w1pack<<<16, 256>>>(ew1);
    cudaEventRecord(evFork, 0);
    cudaStreamWaitEvent(sB, evFork, 0);
    cudaStreamWaitEvent(sC, evFork, 0);

    // k12 producers (2-way concurrency, front-loaded)
    k12_fused<<<c0 / 32, 256, 0, sB>>>(x, eb1, ew2, eb2, hw1, hb1, base0);
    cudaEventRecord(e[0], sB);
    k12_fused<<<c1 / 32, 256, 0, sC>>>(x, eb1, ew2, eb2, hw1, hb1, base1);
    cudaEventRecord(e[1], sC);
    k12_fused<<<c2 / 32, 256, 0, sB>>>(x, eb1, ew2, eb2, hw1, hb1, base2);
    cudaEventRecord(e[2], sB);
    k12_fused<<<c3 / 32, 256, 0, sC>>>(x, eb1, ew2, eb2, hw1, hb1, base3);
    cudaEventRecord(e[3], sC);

    // w2 transpose (needed only by k3) on the default stream, concurrent with k12s
    k_w2split<<<(1296 * 128 + 255) / 256, 256>>>(hw2);
    cudaEventRecord(evW2, 0);
    cudaStreamWaitEvent(sA, evW2, 0);

    // k3 consumer chain (tensor-bound; serialized = continuously busy tensor pipe)
    cudaStreamWaitEvent(sA, e[0], 0);
    k3_mma<<<dim3(9, c0 / 128), 256, K3_SMEM, sA>>>(hb2, out, base0);
    cudaStreamWaitEvent(sA, e[1], 0);
    k3_mma<<<dim3(9, c1 / 128), 256, K3_SMEM, sA>>>(hb2, out, base1);
    cudaStreamWaitEvent(sA, e[2], 0);
    k3_mma<<<dim3(9, c2 / 128), 256, K3_SMEM, sA>>>(hb2, out, base2);
    cudaStreamWaitEvent(sA, e[3], 0);
    k3_mma<<<dim3(9, c3 / 128), 256, K3_SMEM, sA>>>(hb2, out, base3);

    // join
    cudaEventRecord(evJA, sA);
    cudaEventRecord(evJB, sB);
    cudaEventRecord(evJC, sC);
    cudaStreamWaitEvent(0, evJA, 0);
    cudaStreamWaitEvent(0, evJB, 0);
    cudaStreamWaitEvent(0, evJC, 0);
}

// round 14
// speedup vs baseline: 1.0951x; 1.0951x over previous
#include <cuda_runtime.h>
#include <cuda_fp16.h>
#include <cstdint>

typedef unsigned long long ull;

#define BMAX 32768

// ---------------- scratch (static device globals: no allocation) ----------------
__device__ __align__(16) float g_rot[18 * 8];
__device__ __align__(16) __half g_af[(size_t)BMAX * 128];  // A (activations) fp16
__device__ __align__(16) __half g_bh[1296 * 128];          // w2^T fp16 [N,K]
__device__ __align__(16) __half g_w1p[32 * 32 * 4 * 8];    // enc_w1 packed frags hi/lo

// ---------------- f32x2 packed helpers ----------------
__device__ __forceinline__ ull f2pack(float a, float b) {
    ull r;
    asm("mov.b64 %0, {%1, %2};" : "=l"(r) : "r"(__float_as_uint(a)), "r"(__float_as_uint(b)));
    return r;
}
__device__ __forceinline__ void f2unpack(ull v, float& a, float& b) {
    unsigned int lo, hi;
    asm("mov.b64 {%0, %1}, %2;" : "=r"(lo), "=r"(hi) : "l"(v));
    a = __uint_as_float(lo); b = __uint_as_float(hi);
}
__device__ __forceinline__ ull ffma2(ull a, ull b, ull c) {
    ull d;
    asm("fma.rn.f32x2 %0, %1, %2, %3;" : "=l"(d) : "l"(a), "l"(b), "l"(c));
    return d;
}
__device__ __forceinline__ ull fmul2(ull a, ull b) {
    ull d;
    asm("mul.rn.f32x2 %0, %1, %2;" : "=l"(d) : "l"(a), "l"(b));
    return d;
}

// ---------------- mma/ldmatrix/cp.async helpers ----------------
__device__ __forceinline__ uint32_t smem_u32(const void* p) {
    uint32_t a;
    asm("{ .reg .u64 t; cvta.to.shared.u64 t, %1; cvt.u32.u64 %0, t; }" : "=r"(a) : "l"(p));
    return a;
}
__device__ __forceinline__ void ldsm4(uint32_t& r0, uint32_t& r1, uint32_t& r2, uint32_t& r3,
                                      uint32_t a) {
    asm volatile("ldmatrix.sync.aligned.m8n8.x4.shared.b16 {%0,%1,%2,%3}, [%4];"
                 : "=r"(r0), "=r"(r1), "=r"(r2), "=r"(r3) : "r"(a));
}
__device__ __forceinline__ void mma16816(float* d, uint32_t a0, uint32_t a1, uint32_t a2,
                                         uint32_t a3, uint32_t b0, uint32_t b1) {
    asm volatile(
        "mma.sync.aligned.m16n8k16.row.col.f32.f16.f16.f32 "
        "{%0,%1,%2,%3}, {%4,%5,%6,%7}, {%8,%9}, {%0,%1,%2,%3};"
        : "+f"(d[0]), "+f"(d[1]), "+f"(d[2]), "+f"(d[3])
        : "r"(a0), "r"(a1), "r"(a2), "r"(a3), "r"(b0), "r"(b1));
}
__device__ __forceinline__ uint32_t smaddr(uint32_t base, int row, int c) {
    return base + row * 256 + (((uint32_t)(c ^ (row & 7))) << 4);
}
__device__ __forceinline__ uint32_t h2pack(float a, float b) {
    __half2 h = __floats2half2_rn(a, b);
    return *(uint32_t*)&h;
}
__device__ __forceinline__ void cp16(uint32_t dst, const float* src) {
    asm volatile("cp.async.cg.shared.global [%0], [%1], 16;" :: "r"(dst), "l"(src) : "memory");
}
__device__ __forceinline__ void cpcommit() {
    asm volatile("cp.async.commit_group;" ::: "memory");
}
template <int N>
__device__ __forceinline__ void cpwait() {
    asm volatile("cp.async.wait_group %0;" :: "n"(N) : "memory");
}

// ---------------- K0: precompute Rot matrices ----------------
__global__ void k0_rot(const float* __restrict__ qw) {
    int t = threadIdx.x;
    if (t >= 18) return;
    float phi = qw[t * 3 + 0], th = qw[t * 3 + 1], om = qw[t * 3 + 2];
    float c = cosf(th * 0.5f), s = sinf(th * 0.5f);
    float ap = -(phi + om) * 0.5f, am = -(phi - om) * 0.5f;
    float sp, cp, sm, cm;
    sincosf(ap, &sp, &cp);
    sincosf(am, &sm, &cm);
    float* r = g_rot + t * 8;
    r[0] = cp * c;  r[1] = sp * c;
    r[2] = -cm * s; r[3] = sm * s;
    r[4] = cm * s;  r[5] = sm * s;
    r[6] = cp * c;  r[7] = -sp * c;
}

// ---------------- K0b: transpose head_w2 [128,1296] -> fp16 [1296,128] ----------------
__global__ void k_w2split(const float* __restrict__ w2) {
    int i = blockIdx.x * blockDim.x + threadIdx.x;
    if (i >= 1296 * 128) return;
    int n = i >> 7, k = i & 127;
    g_bh[i] = __float2half_rn(w2[k * 1296 + n]);
}

// ---------------- K0c: pack enc_w1 into mma-fragment order, fp16 hi/lo ----
__global__ void k_w1pack(const float* __restrict__ w1) {
    int i = blockIdx.x * blockDim.x + threadIdx.x;
    if (i >= 4096) return;
    int q = i & 3, ks = (i >> 2) & 31, n = i >> 7;
    int kc = ks * 16 + 4 * q;
    float v0 = w1[(kc + 0) * 32 + n];
    float v1 = w1[(kc + 1) * 32 + n];
    float v2 = w1[(kc + 2) * 32 + n];
    float v3 = w1[(kc + 3) * 32 + n];
    __half h[8];
    h[0] = __float2half_rn(v0); h[1] = __float2half_rn(v1);
    h[2] = __float2half_rn(v2); h[3] = __float2half_rn(v3);
    h[4] = __float2half_rn(v0 - __half2float(h[0]));
    h[5] = __float2half_rn(v1 - __half2float(h[1]));
    h[6] = __float2half_rn(v2 - __half2float(h[2]));
    h[7] = __float2half_rn(v3 - __half2float(h[3]));
    *(uint4*)(g_w1p + (size_t)i * 8) = *(uint4*)h;
}

// ---------------- circuit helpers ----------------
__device__ __forceinline__ float2 shflx(float2 v, int m) {
    float2 r;
    r.x = __shfl_xor_sync(0xffffffffu, v.x, m);
    r.y = __shfl_xor_sync(0xffffffffu, v.y, m);
    return r;
}
__device__ __forceinline__ float2 cmul(float2 a, float2 b) {
    return make_float2(a.x * b.x - a.y * b.y, a.x * b.y + a.y * b.x);
}
__device__ __forceinline__ float2 cmadd(float2 a, float2 b, float2 acc) {
    return make_float2(acc.x + a.x * b.x - a.y * b.y, acc.y + a.x * b.y + a.y * b.x);
}

// ---------------- K12: fused encoder (HMMA, cp.async-pipelined) + circuit ----------------
__global__ __launch_bounds__(256)
void k12_fused(const float* __restrict__ x,
               const float* __restrict__ b1,
               const float* __restrict__ w2,
               const float* __restrict__ b2,
               const float* __restrict__ hw1,
               const float* __restrict__ hb1, int base) {
    __shared__ float4 xst[4][256][2];   // 32 KB cp.async staging (per-thread private slots)
    __shared__ float red[2][3][32][16];
    __shared__ float sang[32][6];

    int tid = threadIdx.x, lane = tid & 31, wid = tid >> 5;

    // ======== phase 1: encoder ========
    {
        int tile = wid >> 2, tw = wid & 3;
        int m0 = base + blockIdx.x * 32 + tile * 16;
        int g = lane >> 2, q = lane & 3;
        const float* xr0 = x + (size_t)(m0 + g) * 512;
        const float* xr1 = x + (size_t)(m0 + g + 8) * 512;

        uint32_t xb = smem_u32(&xst[0][tid][0]);  // stage stride 8192 B

        // prime 4-stage pipeline
#pragma unroll
        for (int kk = 0; kk < 4; kk++) {
            int kc = (tw * 8 + kk) * 16 + 4 * q;
            cp16(xb + kk * 8192, xr0 + kc);
            cp16(xb + kk * 8192 + 16, xr1 + kc);
            cpcommit();
        }

        float acc[4][4];
#pragma unroll
        for (int nf = 0; nf < 4; nf++)
#pragma unroll
            for (int v = 0; v < 4; v++) acc[nf][v] = 0.f;

#pragma unroll
        for (int kk = 0; kk < 8; kk++) {
            // wait until stage kk's group has landed
            if (kk <= 4) cpwait<3>();
            else if (kk == 5) cpwait<2>();
            else if (kk == 6) cpwait<1>();
            else cpwait<0>();

            float4 v0 = xst[kk & 3][tid][0];
            float4 v1 = xst[kk & 3][tid][1];

            // refill this stage for kk+4
            if (kk < 4) {
                int kc = (tw * 8 + kk + 4) * 16 + 4 * q;
                cp16(xb + (kk & 3) * 8192, xr0 + kc);
                cp16(xb + (kk & 3) * 8192 + 16, xr1 + kc);
                cpcommit();
            }

            int ks = tw * 8 + kk;
            uint32_t ah0 = h2pack(v0.x, v0.y), ah1 = h2pack(v1.x, v1.y);
            uint32_t ah2 = h2pack(v0.z, v0.w), ah3 = h2pack(v1.z, v1.w);
            __half2 t0 = *(__half2*)&ah0, t1 = *(__half2*)&ah1;
            __half2 t2 = *(__half2*)&ah2, t3 = *(__half2*)&ah3;
            uint32_t al0 = h2pack(v0.x - __low2float(t0), v0.y - __high2float(t0));
            uint32_t al1 = h2pack(v1.x - __low2float(t1), v1.y - __high2float(t1));
            uint32_t al2 = h2pack(v0.z - __low2float(t2), v0.w - __high2float(t2));
            uint32_t al3 = h2pack(v1.z - __low2float(t3), v1.w - __high2float(t3));

#pragma unroll
            for (int nf = 0; nf < 4; nf++) {
                int n = nf * 8 + g;
                uint4 bv = *(const uint4*)(g_w1p + (size_t)(((n * 32 + ks) * 4 + q)) * 8);
                mma16816(acc[nf], ah0, ah1, ah2, ah3, bv.x, bv.y);
                mma16816(acc[nf], ah0, ah1, ah2, ah3, bv.z, bv.w);
                mma16816(acc[nf], al0, al1, al2, al3, bv.x, bv.y);
            }
        }

        if (tw) {
            float4* dst = (float4*)red[tile][tw - 1][lane];
#pragma unroll
            for (int nf = 0; nf < 4; nf++) dst[nf] = *(float4*)acc[nf];
        }
        __syncthreads();

        if (tw == 0) {
#pragma unroll
            for (int w = 0; w < 3; w++) {
                const float* src = red[tile][w][lane];
#pragma unroll
                for (int nf = 0; nf < 4; nf++)
#pragma unroll
                    for (int v = 0; v < 4; v++) acc[nf][v] += src[nf * 4 + v];
            }

            float pr0[6], pr1[6];
#pragma unroll
            for (int i = 0; i < 6; i++) { pr0[i] = 0.f; pr1[i] = 0.f; }

#pragma unroll
            for (int nf = 0; nf < 4; nf++) {
                int c0 = nf * 8 + 2 * q;
                float bb0 = b1[c0], bb1 = b1[c0 + 1];
                float h00 = tanhf(acc[nf][0] + bb0);
                float h01 = tanhf(acc[nf][1] + bb1);
                float h10 = tanhf(acc[nf][2] + bb0);
                float h11 = tanhf(acc[nf][3] + bb1);
#pragma unroll
                for (int i = 0; i < 6; i++) {
                    float w0 = w2[c0 * 6 + i], w1v = w2[(c0 + 1) * 6 + i];
                    pr0[i] += h00 * w0 + h01 * w1v;
                    pr1[i] += h10 * w0 + h11 * w1v;
                }
            }
#pragma unroll
            for (int m = 1; m <= 2; m <<= 1) {
#pragma unroll
                for (int i = 0; i < 6; i++) {
                    pr0[i] += __shfl_xor_sync(0xffffffffu, pr0[i], m);
                    pr1[i] += __shfl_xor_sync(0xffffffffu, pr1[i], m);
                }
            }
            if (q == 0) {
#pragma unroll
                for (int i = 0; i < 6; i++) {
                    sang[tile * 16 + g][i] = pr0[i] + b2[i];
                    sang[tile * 16 + g + 8][i] = pr1[i] + b2[i];
                }
            }
        }
    }
    __syncthreads();

    // ======== phase 2: circuit (4 samples/warp, 8 lanes/sample) ========
    int l3 = lane & 7;
    int ls = wid * 4 + (lane >> 3);
    int s = base + blockIdx.x * 32 + ls;

    float cs[6], sn[6];
#pragma unroll
    for (int q = 0; q < 6; q++) {
        float a = sang[ls][q];
        __sincosf(0.5f * a, &sn[q], &cs[q]);
    }

    float2 A[8];
#pragma unroll
    for (int j = 0; j < 8; j++) A[j] = make_float2(0.f, 0.f);
    if (l3 == 0) A[0].x = 1.f;

#pragma unroll
    for (int L = 0; L < 3; L++) {
#pragma unroll
        for (int q = 0; q < 6; q++) {
            const ull* up = (const ull*)(g_rot + (L * 6 + q) * 8);
            ull u01 = up[0], u23 = up[1], u45 = up[2], u67 = up[3];
            float c = cs[q], s2 = sn[q];
            ull cp = f2pack(c, c), sp = f2pack(s2, s2), sn2 = f2pack(-s2, -s2);
            float2 f00, f01, f10, f11;
            f2unpack(ffma2(u23, sp, fmul2(u01, cp)), f00.x, f00.y);
            f2unpack(ffma2(u01, sn2, fmul2(u23, cp)), f01.x, f01.y);
            f2unpack(ffma2(u67, sp, fmul2(u45, cp)), f10.x, f10.y);
            f2unpack(ffma2(u45, sn2, fmul2(u67, cp)), f11.x, f11.y);

            if (q <= 2) {
                int m = 4 >> q;
                bool hi = (l3 & m) != 0;
                float2 ua = hi ? f11 : f00;
                float2 ub = hi ? f10 : f01;
#pragma unroll
                for (int j = 0; j < 8; j++) {
                    float2 P = shflx(A[j], m);
                    A[j] = cmadd(ub, P, cmul(ua, A[j]));
                }
            } else {
                int lb = 5 - q;
                int st = 1 << lb;
#pragma unroll
                for (int i0 = 0; i0 < 8; i0++) {
                    if (i0 & st) continue;
                    int i1 = i0 | st;
                    float2 n0 = cmadd(f01, A[i1], cmul(f00, A[i0]));
                    float2 n1 = cmadd(f11, A[i1], cmul(f10, A[i0]));
                    A[i0] = n0; A[i1] = n1;
                }
            }
        }
        // CNOT ladder
        {
#pragma unroll
            for (int j = 0; j < 8; j++) {
                float2 P = shflx(A[j], 2);
                if (l3 & 4) A[j] = P;
            }
        }
        if (l3 & 1) {
#pragma unroll
            for (int j = 0; j < 4; j++) { float2 t = A[j]; A[j] = A[j + 4]; A[j + 4] = t; }
        }
        { float2 t = A[2]; A[2] = A[3]; A[3] = t; }
        { float2 t = A[6]; A[6] = A[7]; A[7] = t; }
        {
#pragma unroll
            for (int j = 0; j < 8; j++) {
                float2 P = shflx(A[j], 1);
                if (l3 & 2) A[j] = P;
            }
        }
        { float2 t = A[4]; A[4] = A[6]; A[6] = t; }
        { float2 t = A[5]; A[5] = A[7]; A[7] = t; }
        {
            A[1] = shflx(A[1], 4);
            A[3] = shflx(A[3], 4);
            A[5] = shflx(A[5], 4);
            A[7] = shflx(A[7], 4);
        }
    }

    float p[8];
#pragma unroll
    for (int j = 0; j < 8; j++) p[j] = A[j].x * A[j].x + A[j].y * A[j].y;
    float sum = (p[0] + p[1]) + (p[2] + p[3]) + (p[4] + p[5]) + (p[6] + p[7]);
    float z[6];
    z[0] = (l3 & 4) ? -sum : sum;
    z[1] = (l3 & 2) ? -sum : sum;
    z[2] = (l3 & 1) ? -sum : sum;
    z[3] = sum - 2.f * ((p[4] + p[5]) + (p[6] + p[7]));
    z[4] = sum - 2.f * ((p[2] + p[3]) + (p[6] + p[7]));
    z[5] = sum - 2.f * ((p[1] + p[3]) + (p[5] + p[7]));
#pragma unroll
    for (int off = 4; off; off >>= 1) {
#pragma unroll
        for (int q = 0; q < 6; q++) z[q] += __shfl_xor_sync(0xffffffffu, z[q], off);
    }

    __half hv[16];
#pragma unroll
    for (int u = 0; u < 16; u++) {
        int j = l3 * 16 + u;
        float a = hb1[j];
#pragma unroll
        for (int i = 0; i < 6; i++) a += z[i] * hw1[i * 128 + j];
        hv[u] = __float2half_rn(fmaxf(a, 0.f));
    }
    uint4* dst = (uint4*)(g_af + (size_t)s * 128 + l3 * 16);
    dst[0] = *(uint4*)&hv[0];
    dst[1] = *(uint4*)&hv[8];
}

// ---------------- K3: HMMA fp16 GEMM  out = A[B,128] @ w2[128,1296] + b2 ----
#define K3_SMEM (32768 + 36864)

__global__ __launch_bounds__(256, 2)
void k3_mma(const float* __restrict__ b2, float* __restrict__ out, int base) {
    extern __shared__ char sm3[];
    __half* sA  = (__half*)sm3;            // 128 x 128
    __half* sBh = (__half*)(sm3 + 32768);  // 144 x 128

    int tid = threadIdx.x, lane = tid & 31, wid = tid >> 5;
    int n0 = blockIdx.x * 144;
    int m0 = base + blockIdx.y * 128;

    const uint4* gA = (const uint4*)g_af + (size_t)m0 * 16;
    uint4* dA = (uint4*)sA;
#pragma unroll
    for (int it = 0; it < 8; it++) {
        int i = it * 256 + tid;
        int r = i >> 4, c = i & 15;
        dA[r * 16 + (c ^ (r & 7))] = gA[i];
    }
    const uint4* gBh = (const uint4*)g_bh + (size_t)n0 * 16;
    uint4* dBh = (uint4*)sBh;
#pragma unroll
    for (int it = 0; it < 9; it++) {
        int i = it * 256 + tid;
        int r = i >> 4, c = i & 15;
        dBh[r * 16 + (c ^ (r & 7))] = gBh[i];
    }
    __syncthreads();

    uint32_t sAb = smem_u32(sA), sBhb = smem_u32(sBh);
    int la = lane & 7, hb = (lane >> 3) & 1, hc = lane >> 4;
    int arow = wid * 16 + la + (hb << 3);
    int brow = la + (hb << 3);

    float acc[18][4];
#pragma unroll
    for (int j = 0; j < 18; j++)
#pragma unroll
        for (int v = 0; v < 4; v++) acc[j][v] = 0.f;

#pragma unroll
    for (int ks = 0; ks < 8; ks++) {
        int ca = 2 * ks + hc;
        uint32_t a0, a1, a2, a3;
        ldsm4(a0, a1, a2, a3, smaddr(sAb, arow, ca));

#pragma unroll
        for (int p = 0; p < 9; p++) {
            uint32_t r0, r1, r2, r3;
            ldsm4(r0, r1, r2, r3, smaddr(sBhb, p * 16 + brow, ca));
            mma16816(acc[2 * p],     a0, a1, a2, a3, r0, r2);
            mma16816(acc[2 * p + 1], a0, a1, a2, a3, r1, r3);
        }
    }

    int orow0 = m0 + wid * 16 + (lane >> 2);
    float* op = out + (size_t)orow0 * 1296 + n0 + 2 * (lane & 3);
    const float* bp = b2 + n0 + 2 * (lane & 3);
#pragma unroll
    for (int j = 0; j < 18; j++) {
        float2 bias = *(const float2*)(bp + 8 * j);
        float2 v0 = make_float2(acc[j][0] + bias.x, acc[j][1] + bias.y);
        float2 v1 = make_float2(acc[j][2] + bias.x, acc[j][3] + bias.y);
        __stcs((float2*)(op + 8 * j), v0);
        __stcs((float2*)(op + 8 * j + 8 * 1296), v1);
    }
}

// ---------------- launch: R12 schedule (symmetric 2-stream, overlapped prep) ----------------
extern "C" void kernel_launch(void* const* d_in, const int* in_sizes, int n_in,
                              void* d_out, int out_size) {
    const float* x   = (const float*)d_in[0];
    const float* ew1 = (const float*)d_in[1];
    const float* eb1 = (const float*)d_in[2];
    const float* ew2 = (const float*)d_in[3];
    const float* eb2 = (const float*)d_in[4];
    const float* qw  = (const float*)d_in[5];
    const float* hw1 = (const float*)d_in[6];
    const float* hb1 = (const float*)d_in[7];
    const float* hw2 = (const float*)d_in[8];
    const float* hb2 = (const float*)d_in[9];
    float* out = (float*)d_out;

    int B = in_sizes[0] / 512;

    static bool inited = false;
    static cudaStream_t st[2];
    static cudaEvent_t evFork, evW2, evJoin0, evJoin1;
    if (!inited) {
        cudaStreamCreateWithFlags(&st[0], cudaStreamNonBlocking);
        cudaStreamCreateWithFlags(&st[1], cudaStreamNonBlocking);
        cudaEventCreateWithFlags(&evFork, cudaEventDisableTiming);
        cudaEventCreateWithFlags(&evW2, cudaEventDisableTiming);
        cudaEventCreateWithFlags(&evJoin0, cudaEventDisableTiming);
        cudaEventCreateWithFlags(&evJoin1, cudaEventDisableTiming);
        cudaFuncSetAttribute(k3_mma, cudaFuncAttributeMaxDynamicSharedMemorySize, K3_SMEM);
        inited = true;
    }

    // prep needed by k12 (tiny) on the capture stream
    k0_rot<<<1, 32>>>(qw);
    k_w1pack<<<16, 256>>>(ew1);

    // fork
    cudaEventRecord(evFork, 0);
    cudaStreamWaitEvent(st[0], evFork, 0);
    cudaStreamWaitEvent(st[1], evFork, 0);

    int chunk = B / 2;  // 16384

    // k12 on both streams immediately
    k12_fused<<<chunk / 32, 256, 0, st[0]>>>(x, eb1, ew2, eb2, hw1, hb1, 0);
    k12_fused<<<chunk / 32, 256, 0, st[1]>>>(x, eb1, ew2, eb2, hw1, hb1, chunk);

    // w2 transpose (needed only by k3) runs concurrently on the default stream
    k_w2split<<<(1296 * 128 + 255) / 256, 256>>>(hw2);
    cudaEventRecord(evW2, 0);
    cudaStreamWaitEvent(st[0], evW2, 0);
    cudaStreamWaitEvent(st[1], evW2, 0);

    dim3 g3(9, chunk / 128);
    k3_mma<<<g3, 256, K3_SMEM, st[0]>>>(hb2, out, 0);
    k3_mma<<<g3, 256, K3_SMEM, st[1]>>>(hb2, out, chunk);

    // join
    cudaEventRecord(evJoin0, st[0]);
    cudaEventRecord(evJoin1, st[1]);
    cudaStreamWaitEvent(0, evJoin0, 0);
    cudaStreamWaitEvent(0, evJoin1, 0);
}

// round 15
// speedup vs baseline: 1.1031x; 1.0073x over previous
#include <cuda_runtime.h>
#include <cuda_fp16.h>
#include <cstdint>

typedef unsigned long long ull;

#define BMAX 32768

// ---------------- scratch (static device globals: no allocation) ----------------
__device__ __align__(16) float g_rot[18 * 8];
__device__ __align__(16) __half g_af[(size_t)BMAX * 128];  // A (activations) fp16
__device__ __align__(16) __half g_bh[1296 * 128];          // w2^T fp16 [N,K]
__device__ __align__(16) __half g_w1p[32 * 32 * 4 * 8];    // enc_w1 packed frags hi/lo

// ---------------- f32x2 packed helpers ----------------
__device__ __forceinline__ ull f2pack(float a, float b) {
    ull r;
    asm("mov.b64 %0, {%1, %2};" : "=l"(r) : "r"(__float_as_uint(a)), "r"(__float_as_uint(b)));
    return r;
}
__device__ __forceinline__ void f2unpack(ull v, float& a, float& b) {
    unsigned int lo, hi;
    asm("mov.b64 {%0, %1}, %2;" : "=r"(lo), "=r"(hi) : "l"(v));
    a = __uint_as_float(lo); b = __uint_as_float(hi);
}
__device__ __forceinline__ ull ffma2(ull a, ull b, ull c) {
    ull d;
    asm("fma.rn.f32x2 %0, %1, %2, %3;" : "=l"(d) : "l"(a), "l"(b), "l"(c));
    return d;
}
__device__ __forceinline__ ull fmul2(ull a, ull b) {
    ull d;
    asm("mul.rn.f32x2 %0, %1, %2;" : "=l"(d) : "l"(a), "l"(b));
    return d;
}

// ---------------- mma/ldmatrix/cp.async helpers ----------------
__device__ __forceinline__ uint32_t smem_u32(const void* p) {
    uint32_t a;
    asm("{ .reg .u64 t; cvta.to.shared.u64 t, %1; cvt.u32.u64 %0, t; }" : "=r"(a) : "l"(p));
    return a;
}
__device__ __forceinline__ void ldsm4(uint32_t& r0, uint32_t& r1, uint32_t& r2, uint32_t& r3,
                                      uint32_t a) {
    asm volatile("ldmatrix.sync.aligned.m8n8.x4.shared.b16 {%0,%1,%2,%3}, [%4];"
                 : "=r"(r0), "=r"(r1), "=r"(r2), "=r"(r3) : "r"(a));
}
__device__ __forceinline__ void mma16816(float* d, uint32_t a0, uint32_t a1, uint32_t a2,
                                         uint32_t a3, uint32_t b0, uint32_t b1) {
    asm volatile(
        "mma.sync.aligned.m16n8k16.row.col.f32.f16.f16.f32 "
        "{%0,%1,%2,%3}, {%4,%5,%6,%7}, {%8,%9}, {%0,%1,%2,%3};"
        : "+f"(d[0]), "+f"(d[1]), "+f"(d[2]), "+f"(d[3])
        : "r"(a0), "r"(a1), "r"(a2), "r"(a3), "r"(b0), "r"(b1));
}
__device__ __forceinline__ uint32_t smaddr(uint32_t base, int row, int c) {
    return base + row * 256 + (((uint32_t)(c ^ (row & 7))) << 4);
}
__device__ __forceinline__ uint32_t h2pack(float a, float b) {
    __half2 h = __floats2half2_rn(a, b);
    return *(uint32_t*)&h;
}
__device__ __forceinline__ void cp16(uint32_t dst, const void* src) {
    asm volatile("cp.async.cg.shared.global [%0], [%1], 16;" :: "r"(dst), "l"(src) : "memory");
}
__device__ __forceinline__ void cpcommit() {
    asm volatile("cp.async.commit_group;" ::: "memory");
}
template <int N>
__device__ __forceinline__ void cpwait() {
    asm volatile("cp.async.wait_group %0;" :: "n"(N) : "memory");
}

// ---------------- K0: precompute Rot matrices ----------------
__global__ void k0_rot(const float* __restrict__ qw) {
    int t = threadIdx.x;
    if (t >= 18) return;
    float phi = qw[t * 3 + 0], th = qw[t * 3 + 1], om = qw[t * 3 + 2];
    float c = cosf(th * 0.5f), s = sinf(th * 0.5f);
    float ap = -(phi + om) * 0.5f, am = -(phi - om) * 0.5f;
    float sp, cp, sm, cm;
    sincosf(ap, &sp, &cp);
    sincosf(am, &sm, &cm);
    float* r = g_rot + t * 8;
    r[0] = cp * c;  r[1] = sp * c;
    r[2] = -cm * s; r[3] = sm * s;
    r[4] = cm * s;  r[5] = sm * s;
    r[6] = cp * c;  r[7] = -sp * c;
}

// ---------------- K0b: transpose head_w2 [128,1296] -> fp16 [1296,128] ----------------
__global__ void k_w2split(const float* __restrict__ w2) {
    int i = blockIdx.x * blockDim.x + threadIdx.x;
    if (i >= 1296 * 128) return;
    int n = i >> 7, k = i & 127;
    g_bh[i] = __float2half_rn(w2[k * 1296 + n]);
}

// ---------------- K0c: pack enc_w1 into mma-fragment order, fp16 hi/lo ----
__global__ void k_w1pack(const float* __restrict__ w1) {
    int i = blockIdx.x * blockDim.x + threadIdx.x;
    if (i >= 4096) return;
    int q = i & 3, ks = (i >> 2) & 31, n = i >> 7;
    int kc = ks * 16 + 4 * q;
    float v0 = w1[(kc + 0) * 32 + n];
    float v1 = w1[(kc + 1) * 32 + n];
    float v2 = w1[(kc + 2) * 32 + n];
    float v3 = w1[(kc + 3) * 32 + n];
    __half h[8];
    h[0] = __float2half_rn(v0); h[1] = __float2half_rn(v1);
    h[2] = __float2half_rn(v2); h[3] = __float2half_rn(v3);
    h[4] = __float2half_rn(v0 - __half2float(h[0]));
    h[5] = __float2half_rn(v1 - __half2float(h[1]));
    h[6] = __float2half_rn(v2 - __half2float(h[2]));
    h[7] = __float2half_rn(v3 - __half2float(h[3]));
    *(uint4*)(g_w1p + (size_t)i * 8) = *(uint4*)h;
}

// ---------------- circuit helpers ----------------
__device__ __forceinline__ float2 shflx(float2 v, int m) {
    float2 r;
    r.x = __shfl_xor_sync(0xffffffffu, v.x, m);
    r.y = __shfl_xor_sync(0xffffffffu, v.y, m);
    return r;
}
__device__ __forceinline__ float2 cmul(float2 a, float2 b) {
    return make_float2(a.x * b.x - a.y * b.y, a.x * b.y + a.y * b.x);
}
__device__ __forceinline__ float2 cmadd(float2 a, float2 b, float2 acc) {
    return make_float2(acc.x + a.x * b.x - a.y * b.y, acc.y + a.x * b.y + a.y * b.x);
}

// ---------------- K12: fused encoder (HMMA) + circuit, 32 samples/CTA (R12 version) ----
__global__ __launch_bounds__(256)
void k12_fused(const float* __restrict__ x,
               const float* __restrict__ b1,
               const float* __restrict__ w2,
               const float* __restrict__ b2,
               const float* __restrict__ hw1,
               const float* __restrict__ hb1, int base) {
    __shared__ float red[2][3][32][16];
    __shared__ float sang[32][6];

    int tid = threadIdx.x, lane = tid & 31, wid = tid >> 5;

    // ======== phase 1: encoder ========
    {
        int tile = wid >> 2, tw = wid & 3;
        int m0 = base + blockIdx.x * 32 + tile * 16;
        int g = lane >> 2, q = lane & 3;
        const float* xr0 = x + (size_t)(m0 + g) * 512;
        const float* xr1 = x + (size_t)(m0 + g + 8) * 512;

        float acc[4][4];
#pragma unroll
        for (int nf = 0; nf < 4; nf++)
#pragma unroll
            for (int v = 0; v < 4; v++) acc[nf][v] = 0.f;

#pragma unroll
        for (int kk = 0; kk < 8; kk++) {
            int ks = tw * 8 + kk;
            int kc = ks * 16 + 4 * q;
            float4 v0 = *(const float4*)(xr0 + kc);
            float4 v1 = *(const float4*)(xr1 + kc);

            uint32_t ah0 = h2pack(v0.x, v0.y), ah1 = h2pack(v1.x, v1.y);
            uint32_t ah2 = h2pack(v0.z, v0.w), ah3 = h2pack(v1.z, v1.w);
            __half2 t0 = *(__half2*)&ah0, t1 = *(__half2*)&ah1;
            __half2 t2 = *(__half2*)&ah2, t3 = *(__half2*)&ah3;
            uint32_t al0 = h2pack(v0.x - __low2float(t0), v0.y - __high2float(t0));
            uint32_t al1 = h2pack(v1.x - __low2float(t1), v1.y - __high2float(t1));
            uint32_t al2 = h2pack(v0.z - __low2float(t2), v0.w - __high2float(t2));
            uint32_t al3 = h2pack(v1.z - __low2float(t3), v1.w - __high2float(t3));

#pragma unroll
            for (int nf = 0; nf < 4; nf++) {
                int n = nf * 8 + g;
                uint4 bv = *(const uint4*)(g_w1p + (size_t)(((n * 32 + ks) * 4 + q)) * 8);
                mma16816(acc[nf], ah0, ah1, ah2, ah3, bv.x, bv.y);
                mma16816(acc[nf], ah0, ah1, ah2, ah3, bv.z, bv.w);
                mma16816(acc[nf], al0, al1, al2, al3, bv.x, bv.y);
            }
        }

        if (tw) {
            float4* dst = (float4*)red[tile][tw - 1][lane];
#pragma unroll
            for (int nf = 0; nf < 4; nf++) dst[nf] = *(float4*)acc[nf];
        }
        __syncthreads();

        if (tw == 0) {
#pragma unroll
            for (int w = 0; w < 3; w++) {
                const float* src = red[tile][w][lane];
#pragma unroll
                for (int nf = 0; nf < 4; nf++)
#pragma unroll
                    for (int v = 0; v < 4; v++) acc[nf][v] += src[nf * 4 + v];
            }

            float pr0[6], pr1[6];
#pragma unroll
            for (int i = 0; i < 6; i++) { pr0[i] = 0.f; pr1[i] = 0.f; }

#pragma unroll
            for (int nf = 0; nf < 4; nf++) {
                int c0 = nf * 8 + 2 * q;
                float bb0 = b1[c0], bb1 = b1[c0 + 1];
                float h00 = tanhf(acc[nf][0] + bb0);
                float h01 = tanhf(acc[nf][1] + bb1);
                float h10 = tanhf(acc[nf][2] + bb0);
                float h11 = tanhf(acc[nf][3] + bb1);
#pragma unroll
                for (int i = 0; i < 6; i++) {
                    float w0 = w2[c0 * 6 + i], w1v = w2[(c0 + 1) * 6 + i];
                    pr0[i] += h00 * w0 + h01 * w1v;
                    pr1[i] += h10 * w0 + h11 * w1v;
                }
            }
#pragma unroll
            for (int m = 1; m <= 2; m <<= 1) {
#pragma unroll
                for (int i = 0; i < 6; i++) {
                    pr0[i] += __shfl_xor_sync(0xffffffffu, pr0[i], m);
                    pr1[i] += __shfl_xor_sync(0xffffffffu, pr1[i], m);
                }
            }
            if (q == 0) {
#pragma unroll
                for (int i = 0; i < 6; i++) {
                    sang[tile * 16 + g][i] = pr0[i] + b2[i];
                    sang[tile * 16 + g + 8][i] = pr1[i] + b2[i];
                }
            }
        }
    }
    __syncthreads();

    // ======== phase 2: circuit (4 samples/warp, 8 lanes/sample) ========
    int l3 = lane & 7;
    int ls = wid * 4 + (lane >> 3);
    int s = base + blockIdx.x * 32 + ls;

    float cs[6], sn[6];
#pragma unroll
    for (int q = 0; q < 6; q++) {
        float a = sang[ls][q];
        __sincosf(0.5f * a, &sn[q], &cs[q]);
    }

    float2 A[8];
#pragma unroll
    for (int j = 0; j < 8; j++) A[j] = make_float2(0.f, 0.f);
    if (l3 == 0) A[0].x = 1.f;

#pragma unroll
    for (int L = 0; L < 3; L++) {
#pragma unroll
        for (int q = 0; q < 6; q++) {
            const ull* up = (const ull*)(g_rot + (L * 6 + q) * 8);
            ull u01 = up[0], u23 = up[1], u45 = up[2], u67 = up[3];
            float c = cs[q], s2 = sn[q];
            ull cp = f2pack(c, c), sp = f2pack(s2, s2), sn2 = f2pack(-s2, -s2);
            float2 f00, f01, f10, f11;
            f2unpack(ffma2(u23, sp, fmul2(u01, cp)), f00.x, f00.y);
            f2unpack(ffma2(u01, sn2, fmul2(u23, cp)), f01.x, f01.y);
            f2unpack(ffma2(u67, sp, fmul2(u45, cp)), f10.x, f10.y);
            f2unpack(ffma2(u45, sn2, fmul2(u67, cp)), f11.x, f11.y);

            if (q <= 2) {
                int m = 4 >> q;
                bool hi = (l3 & m) != 0;
                float2 ua = hi ? f11 : f00;
                float2 ub = hi ? f10 : f01;
#pragma unroll
                for (int j = 0; j < 8; j++) {
                    float2 P = shflx(A[j], m);
                    A[j] = cmadd(ub, P, cmul(ua, A[j]));
                }
            } else {
                int lb = 5 - q;
                int st = 1 << lb;
#pragma unroll
                for (int i0 = 0; i0 < 8; i0++) {
                    if (i0 & st) continue;
                    int i1 = i0 | st;
                    float2 n0 = cmadd(f01, A[i1], cmul(f00, A[i0]));
                    float2 n1 = cmadd(f11, A[i1], cmul(f10, A[i0]));
                    A[i0] = n0; A[i1] = n1;
                }
            }
        }
        // CNOT ladder
        {
#pragma unroll
            for (int j = 0; j < 8; j++) {
                float2 P = shflx(A[j], 2);
                if (l3 & 4) A[j] = P;
            }
        }
        if (l3 & 1) {
#pragma unroll
            for (int j = 0; j < 4; j++) { float2 t = A[j]; A[j] = A[j + 4]; A[j + 4] = t; }
        }
        { float2 t = A[2]; A[2] = A[3]; A[3] = t; }
        { float2 t = A[6]; A[6] = A[7]; A[7] = t; }
        {
#pragma unroll
            for (int j = 0; j < 8; j++) {
                float2 P = shflx(A[j], 1);
                if (l3 & 2) A[j] = P;
            }
        }
        { float2 t = A[4]; A[4] = A[6]; A[6] = t; }
        { float2 t = A[5]; A[5] = A[7]; A[7] = t; }
        {
            A[1] = shflx(A[1], 4);
            A[3] = shflx(A[3], 4);
            A[5] = shflx(A[5], 4);
            A[7] = shflx(A[7], 4);
        }
    }

    float p[8];
#pragma unroll
    for (int j = 0; j < 8; j++) p[j] = A[j].x * A[j].x + A[j].y * A[j].y;
    float sum = (p[0] + p[1]) + (p[2] + p[3]) + (p[4] + p[5]) + (p[6] + p[7]);
    float z[6];
    z[0] = (l3 & 4) ? -sum : sum;
    z[1] = (l3 & 2) ? -sum : sum;
    z[2] = (l3 & 1) ? -sum : sum;
    z[3] = sum - 2.f * ((p[4] + p[5]) + (p[6] + p[7]));
    z[4] = sum - 2.f * ((p[2] + p[3]) + (p[6] + p[7]));
    z[5] = sum - 2.f * ((p[1] + p[3]) + (p[5] + p[7]));
#pragma unroll
    for (int off = 4; off; off >>= 1) {
#pragma unroll
        for (int q = 0; q < 6; q++) z[q] += __shfl_xor_sync(0xffffffffu, z[q], off);
    }

    __half hv[16];
#pragma unroll
    for (int u = 0; u < 16; u++) {
        int j = l3 * 16 + u;
        float a = hb1[j];
#pragma unroll
        for (int i = 0; i < 6; i++) a += z[i] * hw1[i * 128 + j];
        hv[u] = __float2half_rn(fmaxf(a, 0.f));
    }
    uint4* dst = (uint4*)(g_af + (size_t)s * 128 + l3 * 16);
    dst[0] = *(uint4*)&hv[0];
    dst[1] = *(uint4*)&hv[8];
}

// ---------------- K3 v2: B-resident, M-loop, cp.async double-buffered A ----------------
// CTA: N-tile 144 (smem, loaded once) x M-stripe 1024 (8 tiles of 128, streamed).
#define K3_SMEM (2 * 32768 + 36864)

__global__ __launch_bounds__(256, 2)
void k3_mma(const float* __restrict__ b2, float* __restrict__ out, int base) {
    extern __shared__ char sm3[];
    // sA[0]: [0,32768), sA[1]: [32768,65536), sB: [65536, 102400)
    __half* sB = (__half*)(sm3 + 65536);

    int tid = threadIdx.x, lane = tid & 31, wid = tid >> 5;
    int n0 = blockIdx.x * 144;
    int m_begin = base + blockIdx.y * 1024;

    uint32_t sA0 = smem_u32(sm3);
    uint32_t sA1 = sA0 + 32768;
    uint32_t sBb = sA0 + 65536;

    // B tile: load once (144 rows x 16 chunks)
    const uint4* gBh = (const uint4*)g_bh + (size_t)n0 * 16;
    uint4* dBh = (uint4*)sB;
#pragma unroll
    for (int it = 0; it < 9; it++) {
        int i = it * 256 + tid;
        int r = i >> 4, c = i & 15;
        dBh[r * 16 + (c ^ (r & 7))] = gBh[i];
    }

    // A tile cp.async loader: tile t -> buffer buf
    const __half* gA = g_af + (size_t)m_begin * 128;
    auto cpA = [&](uint32_t sbuf, int t) {
#pragma unroll
        for (int it = 0; it < 8; it++) {
            int i = it * 256 + tid;
            int r = i >> 4, c = i & 15;
            cp16(sbuf + r * 256 + ((uint32_t)(c ^ (r & 7)) << 4),
                 gA + (size_t)(t * 128 + r) * 128 + c * 8);
        }
        cpcommit();
    };

    cpA(sA0, 0);
    cpA(sA1, 1);

    int la = lane & 7, hb = (lane >> 3) & 1, hc = lane >> 4;
    int arowbase = wid * 16 + la + (hb << 3);
    int brow = la + (hb << 3);

    for (int t = 0; t < 8; t++) {
        if (t < 7) cpwait<1>(); else cpwait<0>();
        __syncthreads();   // A(t) landed CTA-wide; B also visible (first iter)

        uint32_t sAb = (t & 1) ? sA1 : sA0;

        float acc[18][4];
#pragma unroll
        for (int j = 0; j < 18; j++)
#pragma unroll
            for (int v = 0; v < 4; v++) acc[j][v] = 0.f;

#pragma unroll
        for (int ks = 0; ks < 8; ks++) {
            int ca = 2 * ks + hc;
            uint32_t a0, a1, a2, a3;
            ldsm4(a0, a1, a2, a3, smaddr(sAb, arowbase, ca));

#pragma unroll
            for (int p = 0; p < 9; p++) {
                uint32_t r0, r1, r2, r3;
                ldsm4(r0, r1, r2, r3, smaddr(sBb, p * 16 + brow, ca));
                mma16816(acc[2 * p],     a0, a1, a2, a3, r0, r2);
                mma16816(acc[2 * p + 1], a0, a1, a2, a3, r1, r3);
            }
        }

        // refill the buffer just consumed with tile t+2
        if (t < 6) {
            __syncthreads();  // all warps done reading sA[t&1]
            cpA(sAb, t + 2);
        }

        // epilogue for tile t
        int orow0 = m_begin + t * 128 + wid * 16 + (lane >> 2);
        float* op = out + (size_t)orow0 * 1296 + n0 + 2 * (lane & 3);
        const float* bp = b2 + n0 + 2 * (lane & 3);
#pragma unroll
        for (int j = 0; j < 18; j++) {
            float2 bias = *(const float2*)(bp + 8 * j);
            float2 v0 = make_float2(acc[j][0] + bias.x, acc[j][1] + bias.y);
            float2 v1 = make_float2(acc[j][2] + bias.x, acc[j][3] + bias.y);
            __stcs((float2*)(op + 8 * j), v0);
            __stcs((float2*)(op + 8 * j + 8 * 1296), v1);
        }
    }
}

// ---------------- launch: R12 schedule (symmetric 2-stream, overlapped prep) ----------------
extern "C" void kernel_launch(void* const* d_in, const int* in_sizes, int n_in,
                              void* d_out, int out_size) {
    const float* x   = (const float*)d_in[0];
    const float* ew1 = (const float*)d_in[1];
    const float* eb1 = (const float*)d_in[2];
    const float* ew2 = (const float*)d_in[3];
    const float* eb2 = (const float*)d_in[4];
    const float* qw  = (const float*)d_in[5];
    const float* hw1 = (const float*)d_in[6];
    const float* hb1 = (const float*)d_in[7];
    const float* hw2 = (const float*)d_in[8];
    const float* hb2 = (const float*)d_in[9];
    float* out = (float*)d_out;

    int B = in_sizes[0] / 512;

    static bool inited = false;
    static cudaStream_t st[2];
    static cudaEvent_t evFork, evW2, evJoin0, evJoin1;
    if (!inited) {
        cudaStreamCreateWithFlags(&st[0], cudaStreamNonBlocking);
        cudaStreamCreateWithFlags(&st[1], cudaStreamNonBlocking);
        cudaEventCreateWithFlags(&evFork, cudaEventDisableTiming);
        cudaEventCreateWithFlags(&evW2, cudaEventDisableTiming);
        cudaEventCreateWithFlags(&evJoin0, cudaEventDisableTiming);
        cudaEventCreateWithFlags(&evJoin1, cudaEventDisableTiming);
        cudaFuncSetAttribute(k3_mma, cudaFuncAttributeMaxDynamicSharedMemorySize, K3_SMEM);
        inited = true;
    }

    // prep needed by k12 (tiny) on the capture stream
    k0_rot<<<1, 32>>>(qw);
    k_w1pack<<<16, 256>>>(ew1);

    // fork
    cudaEventRecord(evFork, 0);
    cudaStreamWaitEvent(st[0], evFork, 0);
    cudaStreamWaitEvent(st[1], evFork, 0);

    int chunk = B / 2;  // 16384

    // k12 on both streams immediately
    k12_fused<<<chunk / 32, 256, 0, st[0]>>>(x, eb1, ew2, eb2, hw1, hb1, 0);
    k12_fused<<<chunk / 32, 256, 0, st[1]>>>(x, eb1, ew2, eb2, hw1, hb1, chunk);

    // w2 transpose (needed only by k3) runs concurrently on the default stream
    k_w2split<<<(1296 * 128 + 255) / 256, 256>>>(hw2);
    cudaEventRecord(evW2, 0);
    cudaStreamWaitEvent(st[0], evW2, 0);
    cudaStreamWaitEvent(st[1], evW2, 0);

    dim3 g3(9, chunk / 1024);
    k3_mma<<<g3, 256, K3_SMEM, st[0]>>>(hb2, out, 0);
    k3_mma<<<g3, 256, K3_SMEM, st[1]>>>(hb2, out, chunk);

    // join
    cudaEventRecord(evJoin0, st[0]);
    cudaEventRecord(evJoin1, st[1]);
    cudaStreamWaitEvent(0, evJoin0, 0);
    cudaStreamWaitEvent(0, evJoin1, 0);
}